// round 10
// baseline (speedup 1.0000x reference)
#include <cuda_runtime.h>
#include <cstdint>

// ShapeIndex over (B=16, C=1, H=1536, W=1536) fp32 — rolling rows + shuffle boundaries.
// si = (2/pi)*asin(t),  t = (-N1/sqrt(2)) * rsqrt(N1^2 - 2*u*N2)
//   N1 = (1+q^2)r - 2pqs + (1+p^2)t, N2 = r*t - s^2, u = 1+p^2+q^2
// Difference identities (exactly the reference roll-diffs):
//   P[h][w] = x[h-1][w]-x[h][w] (== ref p),  e[h][w] = x[h][w-1]-x[h][w] (== ref q)
//   r = P[h-1]-P[h],  t = e[w-1]-e[w],  s = P[w-1]-P[w]
// Boundary taps (w0-1, w0-2 columns) come from the left-neighbor lane's registers
// via __shfl_up_sync; only lane 0 of each warp loads them from global.

#define BB 16
#define HH 1536
#define WW 1536
#define EPT 8                  // elements (columns) per thread
#define TPB (WW / EPT)         // 192 threads: one full row per block-row-step
#define ROWS 16                // rows per block

__device__ __forceinline__ float remove_nan(float v) {
    unsigned u = __float_as_uint(v);
    return ((u & 0x7fffffffu) > 0x7f800000u) ? 0.0f : v;
}
__device__ __forceinline__ float sqrt_approx(float x) {
    float r; asm("sqrt.approx.f32 %0, %1;" : "=f"(r) : "f"(x)); return r;
}

__device__ __forceinline__ float si_tail(float p, float q, float r, float t, float s) {
    float p2 = p * p;
    float a  = fmaf(q, q, 1.0f);        // 1+q^2
    float b  = p2 + 1.0f;               // 1+p^2
    float u  = a + p2;                  // 1+p^2+q^2
    float pqs = (p * q) * s;
    float N1 = fmaf(a, r, fmaf(b, t, -2.0f * pqs));
    float N2 = fmaf(r, t, -(s * s));
    float un2 = u * N2;
    float z   = fmaf(N1, N1, -(un2 + un2));        // N1^2 - 2*u*N2
    float tt  = (-0.70710678118654752f * N1) * rsqrtf(z);
    float aa  = fabsf(tt);
    float poly = fmaf(fmaf(fmaf(-0.0119235f, aa, 0.0472761f),
                           aa, -0.1350363f), aa, 0.9999570f);
    float mag = fmaf(-sqrt_approx(1.0f - aa), poly, 1.0f);  // (2/pi)asin(|t|)
    return remove_nan(copysignf(mag, tt));
}

__device__ __forceinline__ void load8(const float* __restrict__ row, int w0, float* v) {
    float4 v0 = *reinterpret_cast<const float4*>(row + w0);
    float4 v1 = *reinterpret_cast<const float4*>(row + w0 + 4);
    v[0]=v0.x; v[1]=v0.y; v[2]=v0.z; v[3]=v0.w;
    v[4]=v1.x; v[5]=v1.y; v[6]=v1.z; v[7]=v1.w;
}

__global__ __launch_bounds__(TPB)
void si_kernel(const float* __restrict__ x, float* __restrict__ out) {
    const int tid  = threadIdx.x;           // 0..191
    const int lane = tid & 31;
    const int h0   = blockIdx.x * ROWS;     // first output row of this block
    const int b    = blockIdx.y;            // 0..15
    const int w0   = tid * EPT;
    const int wm1  = (w0 == 0) ? WW - 1 : w0 - 1;
    const int wm2  = (w0 == 0) ? WW - 2 : w0 - 2;
    const bool ld0 = (lane == 0);           // this lane loads its boundary scalars

    const float* img = x + (size_t)b * (HH * WW);
    float* oimg = out + (size_t)b * (HH * WW);

    const int hm1 = (h0 == 0) ? HH - 1 : h0 - 1;
    const int hm2 = (hm1 == 0) ? HH - 1 : hm1 - 1;

    // Prime: prev = row h0-1, Pprev = vertical diff of row h0-1.
    float prev[EPT], Pprev[EPT];
    load8(img + (size_t)hm1 * WW, w0, prev);
    float prevm1 = ld0 ? img[(size_t)hm1 * WW + wm1] : 0.0f;  // x[h-1][w0-1] (lane 0 only)
    {
        float tmp[EPT];
        load8(img + (size_t)hm2 * WW, w0, tmp);
#pragma unroll
        for (int i = 0; i < EPT; i++) Pprev[i] = tmp[i] - prev[i];
    }

#pragma unroll 4
    for (int j = 0; j < ROWS; j++) {
        const int h = h0 + j;
        const float* rowh = img + (size_t)h * WW;

        float cur[EPT];
        load8(rowh, w0, cur);

        // boundary taps: left-neighbor lane's cur[7], cur[6]; lane 0 loads them.
        float sh7 = __shfl_up_sync(0xffffffffu, cur[EPT - 1], 1);
        float sh6 = __shfl_up_sync(0xffffffffu, cur[EPT - 2], 1);
        float am1 = ld0 ? rowh[wm1] : sh7;     // x[h][w0-1]
        float am2 = ld0 ? rowh[wm2] : sh6;     // x[h][w0-2]

        // vertical 1st diffs (P[0] = col w0-1, P[i+1] = col w0+i)
        float P[EPT + 1];
#pragma unroll
        for (int i = 0; i < EPT; i++) P[i + 1] = prev[i] - cur[i];
        float shP = __shfl_up_sync(0xffffffffu, P[EPT], 1);
        P[0] = ld0 ? (prevm1 - am1) : shP;

        float o[EPT];
        float eprev = am2 - am1;          // e(w0-1)
        float ecur  = am1 - cur[0];       // e(w0)
#pragma unroll
        for (int i = 0; i < EPT; i++) {
            float qq = ecur;
            float tt = eprev - ecur;               // horizontal 2nd diff
            float ss = P[i] - P[i + 1];            // cross diff
            float rr = Pprev[i] - P[i + 1];        // vertical 2nd diff
            o[i] = si_tail(P[i + 1], qq, rr, tt, ss);
            eprev = ecur;
            if (i < EPT - 1) ecur = cur[i] - cur[i + 1];
        }

        float* orow = oimg + (size_t)h * WW;
        *reinterpret_cast<float4*>(orow + w0)     = make_float4(o[0], o[1], o[2], o[3]);
        *reinterpret_cast<float4*>(orow + w0 + 4) = make_float4(o[4], o[5], o[6], o[7]);

        // roll state to next row
#pragma unroll
        for (int i = 0; i < EPT; i++) { Pprev[i] = P[i + 1]; prev[i] = cur[i]; }
        prevm1 = am1;
    }
}

extern "C" void kernel_launch(void* const* d_in, const int* in_sizes, int n_in,
                              void* d_out, int out_size) {
    const float* x = (const float*)d_in[0];
    float* out = (float*)d_out;
    dim3 grid(HH / ROWS, BB, 1);   // 96 x 16 = 1536 blocks of 192 threads
    si_kernel<<<grid, TPB>>>(x, out);
}

// round 11
// speedup vs baseline: 1.0732x; 1.0732x over previous
#include <cuda_runtime.h>
#include <cstdint>

// ShapeIndex over (B=16, C=1, H=1536, W=1536) fp32 — rolling rows (R7 shape)
// + aligned-float4 boundary taps + occupancy bound.
// si = (2/pi)*asin(t),  t = (-N1/sqrt(2)) * rsqrt(N1^2 - 2*u*N2)
//   N1 = (1+q^2)r - 2pqs + (1+p^2)t, N2 = r*t - s^2, u = 1+p^2+q^2
// Difference identities (exactly the reference roll-diffs):
//   P[h][w] = x[h-1][w]-x[h][w] (== ref p),  e[h][w] = x[h][w-1]-x[h][w] (== ref q)
//   r = P[h-1]-P[h],  t = e[w-1]-e[w],  s = P[w-1]-P[w]
// Boundary columns w0-1, w0-2 come from ONE aligned float4 at w0-4 (wrap -> WW-4,
// whose .w/.z are exactly x[WW-1]/x[WW-2] — no divergence).

#define BB 16
#define HH 1536
#define WW 1536
#define EPT 8                  // elements (columns) per thread
#define TPB (WW / EPT)         // 192 threads: one full row per block-row-step
#define ROWS 8                 // rows per block (fully unrolled)

__device__ __forceinline__ float remove_nan(float v) {
    unsigned u = __float_as_uint(v);
    return ((u & 0x7fffffffu) > 0x7f800000u) ? 0.0f : v;
}
__device__ __forceinline__ float sqrt_approx(float x) {
    float r; asm("sqrt.approx.f32 %0, %1;" : "=f"(r) : "f"(x)); return r;
}

__device__ __forceinline__ float si_tail(float p, float q, float r, float t, float s) {
    float p2 = p * p;
    float a  = fmaf(q, q, 1.0f);        // 1+q^2
    float b  = p2 + 1.0f;               // 1+p^2
    float u  = a + p2;                  // 1+p^2+q^2
    float pqs = (p * q) * s;
    float N1 = fmaf(a, r, fmaf(b, t, -2.0f * pqs));
    float N2 = fmaf(r, t, -(s * s));
    float un2 = u * N2;
    float z   = fmaf(N1, N1, -(un2 + un2));        // N1^2 - 2*u*N2
    float tt  = (-0.70710678118654752f * N1) * rsqrtf(z);
    float aa  = fabsf(tt);
    float poly = fmaf(fmaf(fmaf(-0.0119235f, aa, 0.0472761f),
                           aa, -0.1350363f), aa, 0.9999570f);
    float mag = fmaf(-sqrt_approx(1.0f - aa), poly, 1.0f);  // (2/pi)asin(|t|)
    return remove_nan(copysignf(mag, tt));
}

__device__ __forceinline__ void load8(const float* __restrict__ row, int w0, float* v) {
    float4 v0 = *reinterpret_cast<const float4*>(row + w0);
    float4 v1 = *reinterpret_cast<const float4*>(row + w0 + 4);
    v[0]=v0.x; v[1]=v0.y; v[2]=v0.z; v[3]=v0.w;
    v[4]=v1.x; v[5]=v1.y; v[6]=v1.z; v[7]=v1.w;
}

__global__ __launch_bounds__(TPB, 6)
void si_kernel(const float* __restrict__ x, float* __restrict__ out) {
    const int tid = threadIdx.x;            // 0..191
    const int h0  = blockIdx.x * ROWS;      // first output row of this block
    const int b   = blockIdx.y;             // 0..15
    const int w0  = tid * EPT;
    const int wb  = (w0 == 0) ? WW - 4 : w0 - 4;   // aligned boundary vector base

    const float* img = x + (size_t)b * (HH * WW);
    float* oimg = out + (size_t)b * (HH * WW);

    const int hm1 = (h0 == 0) ? HH - 1 : h0 - 1;
    const int hm2 = (hm1 == 0) ? HH - 1 : hm1 - 1;

    // Prime: prev = row h0-1 (+ boundary .w), Pprev = vertical diff of row h0-1.
    float prev[EPT], Pprev[EPT];
    const float* rowp = img + (size_t)hm1 * WW;
    load8(rowp, w0, prev);
    float prevm1 = reinterpret_cast<const float4*>(rowp + wb)->w;  // x[h0-1][w0-1]
    {
        float tmp[EPT];
        load8(img + (size_t)hm2 * WW, w0, tmp);
#pragma unroll
        for (int i = 0; i < EPT; i++) Pprev[i] = tmp[i] - prev[i];
    }

#pragma unroll
    for (int j = 0; j < ROWS; j++) {
        const int h = h0 + j;
        const float* rowh = img + (size_t)h * WW;

        float cur[EPT];
        load8(rowh, w0, cur);
        float4 bv = *reinterpret_cast<const float4*>(rowh + wb);
        float am1 = bv.w;   // x[h][w0-1]  (wrap case: x[h][WW-1])
        float am2 = bv.z;   // x[h][w0-2]  (wrap case: x[h][WW-2])

        // vertical 1st diffs (P[0] = col w0-1, P[i+1] = col w0+i)
        float P[EPT + 1];
        P[0] = prevm1 - am1;
#pragma unroll
        for (int i = 0; i < EPT; i++) P[i + 1] = prev[i] - cur[i];

        float o[EPT];
        float eprev = am2 - am1;          // e(w0-1)
        float ecur  = am1 - cur[0];       // e(w0)
#pragma unroll
        for (int i = 0; i < EPT; i++) {
            float qq = ecur;
            float tt = eprev - ecur;               // horizontal 2nd diff
            float ss = P[i] - P[i + 1];            // cross diff
            float rr = Pprev[i] - P[i + 1];        // vertical 2nd diff
            o[i] = si_tail(P[i + 1], qq, rr, tt, ss);
            eprev = ecur;
            if (i < EPT - 1) ecur = cur[i] - cur[i + 1];
        }

        float* orow = oimg + (size_t)h * WW;
        *reinterpret_cast<float4*>(orow + w0)     = make_float4(o[0], o[1], o[2], o[3]);
        *reinterpret_cast<float4*>(orow + w0 + 4) = make_float4(o[4], o[5], o[6], o[7]);

        // roll state to next row (renamed away by full unroll)
#pragma unroll
        for (int i = 0; i < EPT; i++) { Pprev[i] = P[i + 1]; prev[i] = cur[i]; }
        prevm1 = am1;
    }
}

extern "C" void kernel_launch(void* const* d_in, const int* in_sizes, int n_in,
                              void* d_out, int out_size) {
    const float* x = (const float*)d_in[0];
    float* out = (float*)d_out;
    dim3 grid(HH / ROWS, BB, 1);   // 192 x 16 = 3072 blocks of 192 threads
    si_kernel<<<grid, TPB>>>(x, out);
}